// round 15
// baseline (speedup 1.0000x reference)
#include <cuda_runtime.h>
#include <cuda_bf16.h>
#include <cstdint>

// ---------------- constants ----------------
#define TEMP_INV 10.0f
#define TILE_M   128

// main-kernel smem layout (bytes)
#define PH   136                  // H tile pitch (bf16)
#define PO   68                   // OUT tile pitch (fp32)
#define OFF_W2   34816            // after sH (128*136*2)
#define OFF_WSUM 51200            // after W2 (16384)
#define SMEM_MAIN 51264           // + 64 wsum

#define NU 50000
#define NI 10000

__device__ float g_partials[8192];
__device__ __align__(16) __nv_bfloat16 g_w2[128 * 64];
__device__ __align__(16) __nv_bfloat16 g_up[NU * 128];
__device__ __align__(16) __nv_bfloat16 g_ip[NI * 128];

// ---------------- PTX helpers ----------------
__device__ __forceinline__ uint32_t sptr(const void* p) {
    return (uint32_t)__cvta_generic_to_shared(p);
}
__device__ __forceinline__ void ldm_x4(uint32_t a, uint32_t& r0, uint32_t& r1,
                                       uint32_t& r2, uint32_t& r3) {
    asm volatile("ldmatrix.sync.aligned.m8n8.x4.shared.b16 {%0,%1,%2,%3}, [%4];"
                 : "=r"(r0), "=r"(r1), "=r"(r2), "=r"(r3) : "r"(a));
}
__device__ __forceinline__ void ldm_x4_t(uint32_t a, uint32_t& r0, uint32_t& r1,
                                         uint32_t& r2, uint32_t& r3) {
    asm volatile("ldmatrix.sync.aligned.m8n8.x4.trans.shared.b16 {%0,%1,%2,%3}, [%4];"
                 : "=r"(r0), "=r"(r1), "=r"(r2), "=r"(r3) : "r"(a));
}
__device__ __forceinline__ void mma16816(float* d, const uint32_t* a,
                                         uint32_t b0, uint32_t b1) {
    asm volatile(
        "mma.sync.aligned.m16n8k16.row.col.f32.bf16.bf16.f32 "
        "{%0,%1,%2,%3}, {%4,%5,%6,%7}, {%8,%9}, {%0,%1,%2,%3};"
        : "+f"(d[0]), "+f"(d[1]), "+f"(d[2]), "+f"(d[3])
        : "r"(a[0]), "r"(a[1]), "r"(a[2]), "r"(a[3]), "r"(b0), "r"(b1));
}
__device__ __forceinline__ void cpa16(uint32_t dst, const void* src) {
    asm volatile("cp.async.ca.shared.global [%0], [%1], 16;"
                 :: "r"(dst), "l"(src) : "memory");
}
__device__ __forceinline__ void cp_commit() {
    asm volatile("cp.async.commit_group;" ::: "memory");
}
template <int N> __device__ __forceinline__ void cp_wait() {
    asm volatile("cp.async.wait_group %0;" :: "n"(N) : "memory");
}
// streaming (evict-first) float4 load — once-read stream stays out of L2 set
__device__ __forceinline__ float4 ldcs4(const float* p) {
    float4 v;
    asm volatile("ld.global.cs.v4.f32 {%0,%1,%2,%3}, [%4];"
                 : "=f"(v.x), "=f"(v.y), "=f"(v.z), "=f"(v.w) : "l"(p));
    return v;
}
// L2 prefetch (no register result, no fault semantics needed on valid range)
__device__ __forceinline__ void pfL2(const void* p) {
    asm volatile("prefetch.global.L2 [%0];" :: "l"(p));
}

// ================= precompute: U' = ufeat@W1u, I' = ifeat@W1i (bf16 out) ====
// W1 consumed directly from fp32 (convert-on-stage); block 0 also converts W2.
__global__ void __launch_bounds__(256, 2) precompute_kernel(
    const float* __restrict__ ufeat, const float* __restrict__ ifeat,
    const float* __restrict__ W1, const float* __restrict__ W2, int nU_blk)
{
    extern __shared__ char smem[];
    const uint32_t sA_su = sptr(smem);
    const uint32_t sW_su = sA_su + 32768;

    const int tid = threadIdx.x;
    const int lane = tid & 31;
    const int wid = tid >> 5;

    const bool bu = (int)blockIdx.x < nU_blk;
    const int rowbase = (bu ? blockIdx.x : blockIdx.x - nU_blk) * 128;
    const int nrows = bu ? NU : NI;
    const float* __restrict__ srcf = bu ? ufeat : ifeat;
    const float* __restrict__ wsrc = W1 + (bu ? 0 : 128 * 128);
    __nv_bfloat16* __restrict__ outp = bu ? g_up : g_ip;

    // block 0: convert W2 fp32 -> g_w2 bf16 (fused kernel launches after)
    if (blockIdx.x == 0) {
        #pragma unroll
        for (int i = tid; i < 128 * 64; i += 256)
            g_w2[i] = __float2bfloat16(W2[i]);
    }

    // stage W1 half: fp32 -> bf16, swizzled (128 rows x 16 units)
    #pragma unroll
    for (int i = tid; i < 2048; i += 256) {
        int r = i >> 4, u = i & 15;
        const float* p = wsrc + (size_t)r * 128 + u * 8;
        float4 v0 = *(const float4*)p;
        float4 v1 = *(const float4*)(p + 4);
        uint32_t w[4];
        *(__nv_bfloat162*)&w[0] = __floats2bfloat162_rn(v0.x, v0.y);
        *(__nv_bfloat162*)&w[1] = __floats2bfloat162_rn(v0.z, v0.w);
        *(__nv_bfloat162*)&w[2] = __floats2bfloat162_rn(v1.x, v1.y);
        *(__nv_bfloat162*)&w[3] = __floats2bfloat162_rn(v1.z, v1.w);
        uint32_t dsu = sW_su + r * 256 + ((u ^ (r & 7)) << 4);
        asm volatile("st.shared.v4.b32 [%0], {%1,%2,%3,%4};"
                     :: "r"(dsu), "r"(w[0]), "r"(w[1]), "r"(w[2]), "r"(w[3]));
    }

    // stage A tile: fp32 -> bf16, swizzled
    #pragma unroll
    for (int i = tid; i < 2048; i += 256) {
        int r = i >> 4, u = i & 15;
        int rc = rowbase + r; if (rc >= nrows) rc = nrows - 1;
        const float* p = srcf + (size_t)rc * 128 + u * 8;
        float4 v0 = *(const float4*)p;
        float4 v1 = *(const float4*)(p + 4);
        uint32_t w[4];
        *(__nv_bfloat162*)&w[0] = __floats2bfloat162_rn(v0.x, v0.y);
        *(__nv_bfloat162*)&w[1] = __floats2bfloat162_rn(v0.z, v0.w);
        *(__nv_bfloat162*)&w[2] = __floats2bfloat162_rn(v1.x, v1.y);
        *(__nv_bfloat162*)&w[3] = __floats2bfloat162_rn(v1.z, v1.w);
        uint32_t dsu = sA_su + r * 256 + ((u ^ (r & 7)) << 4);
        asm volatile("st.shared.v4.b32 [%0], {%1,%2,%3,%4};"
                     :: "r"(dsu), "r"(w[0]), "r"(w[1]), "r"(w[2]), "r"(w[3]));
    }
    __syncthreads();

    float acc[2][8][4];
    #pragma unroll
    for (int a = 0; a < 2; ++a)
        #pragma unroll
        for (int b = 0; b < 8; ++b)
            #pragma unroll
            for (int c = 0; c < 4; ++c) acc[a][b][c] = 0.f;

    const int wm = (wid & 3) * 32;
    const int wn = (wid >> 2) * 64;

    #pragma unroll
    for (int ks = 0; ks < 8; ++ks) {
        const int u = ks * 2 + (lane >> 4);
        uint32_t a0[4], a1[4];
        {
            int r = wm + (lane & 15);
            ldm_x4(sA_su + r * 256 + ((u ^ (r & 7)) << 4), a0[0], a0[1], a0[2], a0[3]);
            r += 16;
            ldm_x4(sA_su + r * 256 + ((u ^ (r & 7)) << 4), a1[0], a1[1], a1[2], a1[3]);
        }
        const int lr = ks * 16 + (lane & 15);
        #pragma unroll
        for (int nb = 0; nb < 4; ++nb) {
            int cu = (wn >> 3) + nb * 2 + (lane >> 4);
            uint32_t b0, b1, b2, b3;
            ldm_x4_t(sW_su + lr * 256 + ((cu ^ (lr & 7)) << 4), b0, b1, b2, b3);
            mma16816(acc[0][2 * nb],     a0, b0, b1);
            mma16816(acc[0][2 * nb + 1], a0, b2, b3);
            mma16816(acc[1][2 * nb],     a1, b0, b1);
            mma16816(acc[1][2 * nb + 1], a1, b2, b3);
        }
    }

    #pragma unroll
    for (int mi = 0; mi < 2; ++mi)
        #pragma unroll
        for (int nj = 0; nj < 8; ++nj) {
            int row = wm + mi * 16 + (lane >> 2);
            int col = wn + nj * 8 + (lane & 3) * 2;
            float* c = acc[mi][nj];
            int gr0 = rowbase + row, gr1 = gr0 + 8;
            if (gr0 < nrows)
                *(__nv_bfloat162*)&outp[(size_t)gr0 * 128 + col] =
                    __floats2bfloat162_rn(c[0], c[1]);
            if (gr1 < nrows)
                *(__nv_bfloat162*)&outp[(size_t)gr1 * 128 + col] =
                    __floats2bfloat162_rn(c[2], c[3]);
        }
}

// ================= fused per-edge kernel: per-warp pipeline, 1 barrier ======
// (R13/R14 hot path + post-gather L2 prefetch of the warp's stream slice)
__global__ void __launch_bounds__(256, 3) fused_kernel(
    const float* __restrict__ review, const float* __restrict__ negs,
    const int* __restrict__ src, const int* __restrict__ dst, int E,
    int nblk_unused)
{
    extern __shared__ char smem[];
    __nv_bfloat16* sH = (__nv_bfloat16*)smem;
    const uint32_t w2_su = sptr(smem) + OFF_W2;
    float* wSums = (float*)(smem + OFF_WSUM);

    const int tid = threadIdx.x;
    const int lane = tid & 31;
    const int wid = tid >> 5;
    const int base = blockIdx.x * TILE_M;
    const int m0 = wid * 16;

    // stage W2 (swizzled) via cp.async — fetch overlaps the gather below
    #pragma unroll
    for (int i = tid; i < 1024; i += 256) {
        int r = i >> 3, u = i & 7;
        cpa16(w2_su + r * 128 + ((u ^ (r & 7)) << 4), g_w2 + (size_t)r * 64 + u * 8);
    }
    cp_commit();

    // per-warp indices: lanes 0-15 carry src, lanes 16-31 carry dst
    int idxv;
    {
        int e0 = base + m0 + (lane & 15);
        bool ok = (e0 < E);
        idxv = (lane < 16) ? (ok ? src[e0] : src[0])
                           : (ok ? dst[e0] : dst[0]);
    }

    // per-warp gather, one row per iteration: 32 lanes cover 256B (uint2 each)
    #pragma unroll 4
    for (int r16 = 0; r16 < 16; ++r16) {
        int si = __shfl_sync(0xffffffffu, idxv, r16);
        int di = __shfl_sync(0xffffffffu, idxv, 16 + r16);
        uint2 uu = *((const uint2*)(g_up + (size_t)si * 128) + lane);
        uint2 ii = *((const uint2*)(g_ip + (size_t)di * 128) + lane);
        float2 a0 = __bfloat1622float2(*(__nv_bfloat162*)&uu.x);
        float2 b0 = __bfloat1622float2(*(__nv_bfloat162*)&ii.x);
        float2 a1 = __bfloat1622float2(*(__nv_bfloat162*)&uu.y);
        float2 b1 = __bfloat1622float2(*(__nv_bfloat162*)&ii.y);
        uint2 hh;
        *(__nv_bfloat162*)&hh.x = __floats2bfloat162_rn(
            fmaxf(a0.x + b0.x, 0.f), fmaxf(a0.y + b0.y, 0.f));
        *(__nv_bfloat162*)&hh.y = __floats2bfloat162_rn(
            fmaxf(a1.x + b1.x, 0.f), fmaxf(a1.y + b1.y, 0.f));
        *(uint2*)&sH[(m0 + r16) * PH + lane * 4] = hh;
    }

    // ---- L2 prefetch of this warp's epilogue stream slice (16 edges) ----
    // review: 16 rows * 256B = 32 lines; negs: 16 rows * 1280B = 160 lines.
    // Issued AFTER the gather (no LTS competition with table reads); DRAM
    // fetch overlaps GEMM2 + early epilogue compute. Tail CTAs skip.
    if (base + m0 + 15 < E) {
        const char* pr = (const char*)(review + (size_t)(base + m0) * 64);
        pfL2(pr + lane * 128);
        const char* ng = (const char*)(negs + (size_t)(base + m0) * 320);
        #pragma unroll
        for (int i = 0; i < 5; ++i)
            pfL2(ng + (size_t)(lane + i * 32) * 128);
    }

    cp_wait<0>();
    __syncthreads();   // W2 ready; also makes warp's own gather cross-lane visible

    // GEMM2 (per-warp): OUT[m0:m0+16, 0:64] = H[m0:m0+16, :] @ W2
    float acc2[8][4];
    #pragma unroll
    for (int b = 0; b < 8; ++b)
        #pragma unroll
        for (int c = 0; c < 4; ++c) acc2[b][c] = 0.f;

    #pragma unroll
    for (int k = 0; k < 8; ++k) {
        int kg = k * 16;
        uint32_t a[4];
        ldm_x4(sptr(&sH[(m0 + (lane & 15)) * PH + kg + ((lane >> 4) << 3)]),
               a[0], a[1], a[2], a[3]);
        const int lr = kg + (lane & 15);
        #pragma unroll
        for (int nb = 0; nb < 4; ++nb) {
            int cu = nb * 2 + (lane >> 4);
            uint32_t b0, b1, b2, b3;
            ldm_x4_t(w2_su + lr * 128 + ((cu ^ (lr & 7)) << 4), b0, b1, b2, b3);
            mma16816(acc2[2 * nb],     a, b0, b1);
            mma16816(acc2[2 * nb + 1], a, b2, b3);
        }
    }

    // warp's ldmatrix reads of its own rows are complete (warp-synchronous);
    // overwrite the SAME byte range with fp32 OUT.
    float* sOUT = (float*)smem;
    #pragma unroll
    for (int nj = 0; nj < 8; ++nj) {
        int row = m0 + (lane >> 2);
        int col = nj * 8 + (lane & 3) * 2;
        *(float2*)&sOUT[row * PO + col]       = make_float2(acc2[nj][0], acc2[nj][1]);
        *(float2*)&sOUT[(row + 8) * PO + col] = make_float2(acc2[nj][2], acc2[nj][3]);
    }
    __syncwarp();   // cross-lane visibility of OUT within the warp

    // ---- epilogue v4: 4 lanes per edge, 8 edges/pass, 2 shuffle rounds ----
    float lsum = 0.f;
    {
        const int eg = lane >> 2;           // edge within pass group (0..7)
        const int qb = (lane & 3) << 4;     // dim base (0,16,32,48)

        #pragma unroll
        for (int pass = 0; pass < 2; ++pass) {
            const int r = m0 + pass * 8 + eg;
            const long e = base + r;
            const bool valid = (e < E);
            const long ec = valid ? e : 0;
            const float* __restrict__ pr = review + ec * 64 + qb;
            const float* __restrict__ ng = negs + ec * 320 + qb;

            float q[16];
            #pragma unroll
            for (int i = 0; i < 4; ++i) {
                float4 t = *(const float4*)&sOUT[r * PO + qb + 4 * i];
                q[4*i] = t.x; q[4*i+1] = t.y; q[4*i+2] = t.z; q[4*i+3] = t.w;
            }

            float v[13];
            float qq = 0.f;
            #pragma unroll
            for (int i = 0; i < 16; ++i) qq += q[i] * q[i];
            v[0] = qq;
            float qp = 0.f, pp = 0.f;
            #pragma unroll
            for (int i = 0; i < 4; ++i) {
                float4 p4 = ldcs4(pr + 4 * i);
                qp += q[4*i]*p4.x + q[4*i+1]*p4.y + q[4*i+2]*p4.z + q[4*i+3]*p4.w;
                pp += p4.x*p4.x + p4.y*p4.y + p4.z*p4.z + p4.w*p4.w;
            }
            v[1] = qp; v[2] = pp;
            #pragma unroll
            for (int m = 0; m < 5; ++m) {
                const float* nm = ng + m * 64;
                float dq = 0.f, dn = 0.f;
                #pragma unroll
                for (int i = 0; i < 4; ++i) {
                    float4 n4 = ldcs4(nm + 4 * i);
                    dq += q[4*i]*n4.x + q[4*i+1]*n4.y + q[4*i+2]*n4.z + q[4*i+3]*n4.w;
                    dn += n4.x*n4.x + n4.y*n4.y + n4.z*n4.z + n4.w*n4.w;
                }
                v[3 + 2 * m] = dq;
                v[4 + 2 * m] = dn;
            }

            #pragma unroll
            for (int j = 0; j < 13; ++j)
                v[j] += __shfl_xor_sync(0xffffffffu, v[j], 1);
            #pragma unroll
            for (int j = 0; j < 13; ++j)
                v[j] += __shfl_xor_sync(0xffffffffu, v[j], 2);

            float rq = rsqrtf(v[0]);
            float pos = v[1] * rq * rsqrtf(v[2]) * TEMP_INV;
            float mx = pos;
            float lg[5];
            #pragma unroll
            for (int m = 0; m < 5; ++m) {
                lg[m] = v[3 + 2 * m] * rq * rsqrtf(v[4 + 2 * m]) * TEMP_INV;
                mx = fmaxf(mx, lg[m]);
            }
            float s = __expf(pos - mx);
            #pragma unroll
            for (int m = 0; m < 5; ++m) s += __expf(lg[m] - mx);
            float loss = mx + __logf(s) - pos;
            if (valid && (lane & 3) == 0) lsum += loss;
        }
    }

    #pragma unroll
    for (int off = 16; off > 0; off >>= 1)
        lsum += __shfl_xor_sync(0xffffffffu, lsum, off);

    if (lane == 0) wSums[wid] = lsum;
    __syncthreads();
    if (tid == 0) {
        float bs = 0.f;
        #pragma unroll
        for (int w = 0; w < 8; ++w) bs += wSums[w];
        g_partials[blockIdx.x] = bs;
    }
}

// ---------------- finalize ----------------
__global__ void finalize_kernel(float* out, int nblk, int E) {
    __shared__ float sh[256];
    float s = 0.f;
    for (int i = threadIdx.x; i < nblk; i += 256) s += g_partials[i];
    sh[threadIdx.x] = s;
    __syncthreads();
    for (int st = 128; st > 0; st >>= 1) {
        if (threadIdx.x < st) sh[threadIdx.x] += sh[threadIdx.x + st];
        __syncthreads();
    }
    if (threadIdx.x == 0) out[0] = sh[0] / (float)E;
}

// ---------------- launch ----------------
extern "C" void kernel_launch(void* const* d_in, const int* in_sizes, int n_in,
                              void* d_out, int out_size) {
    const float* ufeat  = (const float*)d_in[0];
    const float* ifeat  = (const float*)d_in[1];
    const float* review = (const float*)d_in[2];
    const float* negs   = (const float*)d_in[3];
    const float* W1     = (const float*)d_in[4];
    const float* W2     = (const float*)d_in[5];
    const int*   src    = (const int*)d_in[6];
    const int*   dst    = (const int*)d_in[7];
    (void)n_in; (void)out_size;

    int E = in_sizes[6];
    int nblk = (E + TILE_M - 1) / TILE_M;
    int nU_blk = (NU + 127) / 128;
    int nI_blk = (NI + 127) / 128;

    cudaFuncSetAttribute(precompute_kernel,
                         cudaFuncAttributeMaxDynamicSharedMemorySize, 65536);
    precompute_kernel<<<nU_blk + nI_blk, 256, 65536>>>(ufeat, ifeat, W1, W2, nU_blk);

    cudaFuncSetAttribute(fused_kernel,
                         cudaFuncAttributeMaxDynamicSharedMemorySize, SMEM_MAIN);
    fused_kernel<<<nblk, 256, SMEM_MAIN>>>(review, negs, src, dst, E, nblk);

    finalize_kernel<<<1, 256>>>((float*)d_out, nblk, E);
}

// round 16
// speedup vs baseline: 1.1201x; 1.1201x over previous
#include <cuda_runtime.h>
#include <cuda_bf16.h>
#include <cstdint>

// ---------------- constants ----------------
#define TEMP_INV 10.0f
#define TILE_M   128

// main-kernel smem layout (bytes)
#define PH   136                  // H tile pitch (bf16)
#define PO   68                   // OUT tile pitch (fp32)
#define OFF_W2   34816            // after sH (128*136*2)
#define OFF_WSUM 51200            // after W2 (16384)
#define SMEM_MAIN 51264           // + 64 wsum

#define NU 50000
#define NI 10000

// precompute: 64-row tiles, sA 16KB + sW 32KB
#define PRE_ROWS 64
#define SMEM_PRE 49152

__device__ float g_partials[8192];
__device__ __align__(16) __nv_bfloat16 g_w2[128 * 64];
__device__ __align__(16) __nv_bfloat16 g_up[NU * 128];
__device__ __align__(16) __nv_bfloat16 g_ip[NI * 128];

// ---------------- PTX helpers ----------------
__device__ __forceinline__ uint32_t sptr(const void* p) {
    return (uint32_t)__cvta_generic_to_shared(p);
}
__device__ __forceinline__ void ldm_x4(uint32_t a, uint32_t& r0, uint32_t& r1,
                                       uint32_t& r2, uint32_t& r3) {
    asm volatile("ldmatrix.sync.aligned.m8n8.x4.shared.b16 {%0,%1,%2,%3}, [%4];"
                 : "=r"(r0), "=r"(r1), "=r"(r2), "=r"(r3) : "r"(a));
}
__device__ __forceinline__ void ldm_x4_t(uint32_t a, uint32_t& r0, uint32_t& r1,
                                         uint32_t& r2, uint32_t& r3) {
    asm volatile("ldmatrix.sync.aligned.m8n8.x4.trans.shared.b16 {%0,%1,%2,%3}, [%4];"
                 : "=r"(r0), "=r"(r1), "=r"(r2), "=r"(r3) : "r"(a));
}
__device__ __forceinline__ void mma16816(float* d, const uint32_t* a,
                                         uint32_t b0, uint32_t b1) {
    asm volatile(
        "mma.sync.aligned.m16n8k16.row.col.f32.bf16.bf16.f32 "
        "{%0,%1,%2,%3}, {%4,%5,%6,%7}, {%8,%9}, {%0,%1,%2,%3};"
        : "+f"(d[0]), "+f"(d[1]), "+f"(d[2]), "+f"(d[3])
        : "r"(a[0]), "r"(a[1]), "r"(a[2]), "r"(a[3]), "r"(b0), "r"(b1));
}
__device__ __forceinline__ void cpa16(uint32_t dst, const void* src) {
    asm volatile("cp.async.ca.shared.global [%0], [%1], 16;"
                 :: "r"(dst), "l"(src) : "memory");
}
__device__ __forceinline__ void cp_commit() {
    asm volatile("cp.async.commit_group;" ::: "memory");
}
template <int N> __device__ __forceinline__ void cp_wait() {
    asm volatile("cp.async.wait_group %0;" :: "n"(N) : "memory");
}
// streaming (evict-first) float4 load — once-read stream stays out of L2 set
__device__ __forceinline__ float4 ldcs4(const float* p) {
    float4 v;
    asm volatile("ld.global.cs.v4.f32 {%0,%1,%2,%3}, [%4];"
                 : "=f"(v.x), "=f"(v.y), "=f"(v.z), "=f"(v.w) : "l"(p));
    return v;
}

// ================= precompute: U' = ufeat@W1u, I' = ifeat@W1i (bf16 out) ====
// 64-row tiles (grid ~939), occ-3: halves per-CTA latency chain, smooths tail.
// W1 consumed directly from fp32 (convert-on-stage); block 0 also converts W2.
__global__ void __launch_bounds__(256, 3) precompute_kernel(
    const float* __restrict__ ufeat, const float* __restrict__ ifeat,
    const float* __restrict__ W1, const float* __restrict__ W2, int nU_blk)
{
    extern __shared__ char smem[];
    const uint32_t sA_su = sptr(smem);                    // 64 rows * 256B
    const uint32_t sW_su = sA_su + PRE_ROWS * 256;        // 128 rows * 256B

    const int tid = threadIdx.x;
    const int lane = tid & 31;
    const int wid = tid >> 5;

    const bool bu = (int)blockIdx.x < nU_blk;
    const int rowbase = (bu ? blockIdx.x : blockIdx.x - nU_blk) * PRE_ROWS;
    const int nrows = bu ? NU : NI;
    const float* __restrict__ srcf = bu ? ufeat : ifeat;
    const float* __restrict__ wsrc = W1 + (bu ? 0 : 128 * 128);
    __nv_bfloat16* __restrict__ outp = bu ? g_up : g_ip;

    // block 0: convert W2 fp32 -> g_w2 bf16 (fused kernel launches after)
    if (blockIdx.x == 0) {
        #pragma unroll
        for (int i = tid; i < 128 * 64; i += 256)
            g_w2[i] = __float2bfloat16(W2[i]);
    }

    // stage W1 half: fp32 -> bf16, swizzled (128 rows x 16 units)
    #pragma unroll
    for (int i = tid; i < 2048; i += 256) {
        int r = i >> 4, u = i & 15;
        const float* p = wsrc + (size_t)r * 128 + u * 8;
        float4 v0 = *(const float4*)p;
        float4 v1 = *(const float4*)(p + 4);
        uint32_t w[4];
        *(__nv_bfloat162*)&w[0] = __floats2bfloat162_rn(v0.x, v0.y);
        *(__nv_bfloat162*)&w[1] = __floats2bfloat162_rn(v0.z, v0.w);
        *(__nv_bfloat162*)&w[2] = __floats2bfloat162_rn(v1.x, v1.y);
        *(__nv_bfloat162*)&w[3] = __floats2bfloat162_rn(v1.z, v1.w);
        uint32_t dsu = sW_su + r * 256 + ((u ^ (r & 7)) << 4);
        asm volatile("st.shared.v4.b32 [%0], {%1,%2,%3,%4};"
                     :: "r"(dsu), "r"(w[0]), "r"(w[1]), "r"(w[2]), "r"(w[3]));
    }

    // stage A tile (64 rows): fp32 -> bf16, swizzled
    #pragma unroll
    for (int i = tid; i < PRE_ROWS * 16; i += 256) {
        int r = i >> 4, u = i & 15;
        int rc = rowbase + r; if (rc >= nrows) rc = nrows - 1;
        const float* p = srcf + (size_t)rc * 128 + u * 8;
        float4 v0 = *(const float4*)p;
        float4 v1 = *(const float4*)(p + 4);
        uint32_t w[4];
        *(__nv_bfloat162*)&w[0] = __floats2bfloat162_rn(v0.x, v0.y);
        *(__nv_bfloat162*)&w[1] = __floats2bfloat162_rn(v0.z, v0.w);
        *(__nv_bfloat162*)&w[2] = __floats2bfloat162_rn(v1.x, v1.y);
        *(__nv_bfloat162*)&w[3] = __floats2bfloat162_rn(v1.z, v1.w);
        uint32_t dsu = sA_su + r * 256 + ((u ^ (r & 7)) << 4);
        asm volatile("st.shared.v4.b32 [%0], {%1,%2,%3,%4};"
                     :: "r"(dsu), "r"(w[0]), "r"(w[1]), "r"(w[2]), "r"(w[3]));
    }
    __syncthreads();

    // warp layout: 2 over M (32 rows each) x 4 over N (32 cols each)
    float acc[2][4][4];
    #pragma unroll
    for (int a = 0; a < 2; ++a)
        #pragma unroll
        for (int b = 0; b < 4; ++b)
            #pragma unroll
            for (int c = 0; c < 4; ++c) acc[a][b][c] = 0.f;

    const int wm = (wid & 1) * 32;
    const int wn = (wid >> 1) * 32;

    #pragma unroll
    for (int ks = 0; ks < 8; ++ks) {
        const int u = ks * 2 + (lane >> 4);
        uint32_t a0[4], a1[4];
        {
            int r = wm + (lane & 15);
            ldm_x4(sA_su + r * 256 + ((u ^ (r & 7)) << 4), a0[0], a0[1], a0[2], a0[3]);
            r += 16;
            ldm_x4(sA_su + r * 256 + ((u ^ (r & 7)) << 4), a1[0], a1[1], a1[2], a1[3]);
        }
        const int lr = ks * 16 + (lane & 15);
        #pragma unroll
        for (int nb = 0; nb < 2; ++nb) {
            int cu = (wn >> 3) + nb * 2 + (lane >> 4);
            uint32_t b0, b1, b2, b3;
            ldm_x4_t(sW_su + lr * 256 + ((cu ^ (lr & 7)) << 4), b0, b1, b2, b3);
            mma16816(acc[0][2 * nb],     a0, b0, b1);
            mma16816(acc[0][2 * nb + 1], a0, b2, b3);
            mma16816(acc[1][2 * nb],     a1, b0, b1);
            mma16816(acc[1][2 * nb + 1], a1, b2, b3);
        }
    }

    #pragma unroll
    for (int mi = 0; mi < 2; ++mi)
        #pragma unroll
        for (int nj = 0; nj < 4; ++nj) {
            int row = wm + mi * 16 + (lane >> 2);
            int col = wn + nj * 8 + (lane & 3) * 2;
            float* c = acc[mi][nj];
            int gr0 = rowbase + row, gr1 = gr0 + 8;
            if (gr0 < nrows)
                *(__nv_bfloat162*)&outp[(size_t)gr0 * 128 + col] =
                    __floats2bfloat162_rn(c[0], c[1]);
            if (gr1 < nrows)
                *(__nv_bfloat162*)&outp[(size_t)gr1 * 128 + col] =
                    __floats2bfloat162_rn(c[2], c[3]);
        }
}

// ================= fused per-edge kernel: per-warp pipeline, 1 barrier ======
// (byte-identical hot path to the R14 182.2us winner)
__global__ void __launch_bounds__(256, 3) fused_kernel(
    const float* __restrict__ review, const float* __restrict__ negs,
    const int* __restrict__ src, const int* __restrict__ dst, int E,
    int nblk_unused)
{
    extern __shared__ char smem[];
    __nv_bfloat16* sH = (__nv_bfloat16*)smem;
    const uint32_t w2_su = sptr(smem) + OFF_W2;
    float* wSums = (float*)(smem + OFF_WSUM);

    const int tid = threadIdx.x;
    const int lane = tid & 31;
    const int wid = tid >> 5;
    const int base = blockIdx.x * TILE_M;
    const int m0 = wid * 16;

    // stage W2 (swizzled) via cp.async — fetch overlaps the gather below
    #pragma unroll
    for (int i = tid; i < 1024; i += 256) {
        int r = i >> 3, u = i & 7;
        cpa16(w2_su + r * 128 + ((u ^ (r & 7)) << 4), g_w2 + (size_t)r * 64 + u * 8);
    }
    cp_commit();

    // per-warp indices: lanes 0-15 carry src, lanes 16-31 carry dst
    int idxv;
    {
        int e0 = base + m0 + (lane & 15);
        bool ok = (e0 < E);
        idxv = (lane < 16) ? (ok ? src[e0] : src[0])
                           : (ok ? dst[e0] : dst[0]);
    }

    // per-warp gather, one row per iteration: 32 lanes cover 256B (uint2 each)
    #pragma unroll 4
    for (int r16 = 0; r16 < 16; ++r16) {
        int si = __shfl_sync(0xffffffffu, idxv, r16);
        int di = __shfl_sync(0xffffffffu, idxv, 16 + r16);
        uint2 uu = *((const uint2*)(g_up + (size_t)si * 128) + lane);
        uint2 ii = *((const uint2*)(g_ip + (size_t)di * 128) + lane);
        float2 a0 = __bfloat1622float2(*(__nv_bfloat162*)&uu.x);
        float2 b0 = __bfloat1622float2(*(__nv_bfloat162*)&ii.x);
        float2 a1 = __bfloat1622float2(*(__nv_bfloat162*)&uu.y);
        float2 b1 = __bfloat1622float2(*(__nv_bfloat162*)&ii.y);
        uint2 hh;
        *(__nv_bfloat162*)&hh.x = __floats2bfloat162_rn(
            fmaxf(a0.x + b0.x, 0.f), fmaxf(a0.y + b0.y, 0.f));
        *(__nv_bfloat162*)&hh.y = __floats2bfloat162_rn(
            fmaxf(a1.x + b1.x, 0.f), fmaxf(a1.y + b1.y, 0.f));
        *(uint2*)&sH[(m0 + r16) * PH + lane * 4] = hh;
    }

    cp_wait<0>();
    __syncthreads();   // W2 ready; also makes warp's own gather cross-lane visible

    // GEMM2 (per-warp): OUT[m0:m0+16, 0:64] = H[m0:m0+16, :] @ W2
    float acc2[8][4];
    #pragma unroll
    for (int b = 0; b < 8; ++b)
        #pragma unroll
        for (int c = 0; c < 4; ++c) acc2[b][c] = 0.f;

    #pragma unroll
    for (int k = 0; k < 8; ++k) {
        int kg = k * 16;
        uint32_t a[4];
        ldm_x4(sptr(&sH[(m0 + (lane & 15)) * PH + kg + ((lane >> 4) << 3)]),
               a[0], a[1], a[2], a[3]);
        const int lr = kg + (lane & 15);
        #pragma unroll
        for (int nb = 0; nb < 4; ++nb) {
            int cu = nb * 2 + (lane >> 4);
            uint32_t b0, b1, b2, b3;
            ldm_x4_t(w2_su + lr * 128 + ((cu ^ (lr & 7)) << 4), b0, b1, b2, b3);
            mma16816(acc2[2 * nb],     a, b0, b1);
            mma16816(acc2[2 * nb + 1], a, b2, b3);
        }
    }

    // warp's ldmatrix reads of its own rows are complete (warp-synchronous);
    // overwrite the SAME byte range with fp32 OUT.
    float* sOUT = (float*)smem;
    #pragma unroll
    for (int nj = 0; nj < 8; ++nj) {
        int row = m0 + (lane >> 2);
        int col = nj * 8 + (lane & 3) * 2;
        *(float2*)&sOUT[row * PO + col]       = make_float2(acc2[nj][0], acc2[nj][1]);
        *(float2*)&sOUT[(row + 8) * PO + col] = make_float2(acc2[nj][2], acc2[nj][3]);
    }
    __syncwarp();   // cross-lane visibility of OUT within the warp

    // ---- epilogue v4: 4 lanes per edge, 8 edges/pass, 2 shuffle rounds ----
    float lsum = 0.f;
    {
        const int eg = lane >> 2;           // edge within pass group (0..7)
        const int qb = (lane & 3) << 4;     // dim base (0,16,32,48)

        #pragma unroll
        for (int pass = 0; pass < 2; ++pass) {
            const int r = m0 + pass * 8 + eg;
            const long e = base + r;
            const bool valid = (e < E);
            const long ec = valid ? e : 0;
            const float* __restrict__ pr = review + ec * 64 + qb;
            const float* __restrict__ ng = negs + ec * 320 + qb;

            float q[16];
            #pragma unroll
            for (int i = 0; i < 4; ++i) {
                float4 t = *(const float4*)&sOUT[r * PO + qb + 4 * i];
                q[4*i] = t.x; q[4*i+1] = t.y; q[4*i+2] = t.z; q[4*i+3] = t.w;
            }

            float v[13];
            float qq = 0.f;
            #pragma unroll
            for (int i = 0; i < 16; ++i) qq += q[i] * q[i];
            v[0] = qq;
            float qp = 0.f, pp = 0.f;
            #pragma unroll
            for (int i = 0; i < 4; ++i) {
                float4 p4 = ldcs4(pr + 4 * i);
                qp += q[4*i]*p4.x + q[4*i+1]*p4.y + q[4*i+2]*p4.z + q[4*i+3]*p4.w;
                pp += p4.x*p4.x + p4.y*p4.y + p4.z*p4.z + p4.w*p4.w;
            }
            v[1] = qp; v[2] = pp;
            #pragma unroll
            for (int m = 0; m < 5; ++m) {
                const float* nm = ng + m * 64;
                float dq = 0.f, dn = 0.f;
                #pragma unroll
                for (int i = 0; i < 4; ++i) {
                    float4 n4 = ldcs4(nm + 4 * i);
                    dq += q[4*i]*n4.x + q[4*i+1]*n4.y + q[4*i+2]*n4.z + q[4*i+3]*n4.w;
                    dn += n4.x*n4.x + n4.y*n4.y + n4.z*n4.z + n4.w*n4.w;
                }
                v[3 + 2 * m] = dq;
                v[4 + 2 * m] = dn;
            }

            #pragma unroll
            for (int j = 0; j < 13; ++j)
                v[j] += __shfl_xor_sync(0xffffffffu, v[j], 1);
            #pragma unroll
            for (int j = 0; j < 13; ++j)
                v[j] += __shfl_xor_sync(0xffffffffu, v[j], 2);

            float rq = rsqrtf(v[0]);
            float pos = v[1] * rq * rsqrtf(v[2]) * TEMP_INV;
            float mx = pos;
            float lg[5];
            #pragma unroll
            for (int m = 0; m < 5; ++m) {
                lg[m] = v[3 + 2 * m] * rq * rsqrtf(v[4 + 2 * m]) * TEMP_INV;
                mx = fmaxf(mx, lg[m]);
            }
            float s = __expf(pos - mx);
            #pragma unroll
            for (int m = 0; m < 5; ++m) s += __expf(lg[m] - mx);
            float loss = mx + __logf(s) - pos;
            if (valid && (lane & 3) == 0) lsum += loss;
        }
    }

    #pragma unroll
    for (int off = 16; off > 0; off >>= 1)
        lsum += __shfl_xor_sync(0xffffffffu, lsum, off);

    if (lane == 0) wSums[wid] = lsum;
    __syncthreads();
    if (tid == 0) {
        float bs = 0.f;
        #pragma unroll
        for (int w = 0; w < 8; ++w) bs += wSums[w];
        g_partials[blockIdx.x] = bs;
    }
}

// ---------------- finalize ----------------
__global__ void finalize_kernel(float* out, int nblk, int E) {
    __shared__ float sh[256];
    float s = 0.f;
    for (int i = threadIdx.x; i < nblk; i += 256) s += g_partials[i];
    sh[threadIdx.x] = s;
    __syncthreads();
    for (int st = 128; st > 0; st >>= 1) {
        if (threadIdx.x < st) sh[threadIdx.x] += sh[threadIdx.x + st];
        __syncthreads();
    }
    if (threadIdx.x == 0) out[0] = sh[0] / (float)E;
}

// ---------------- launch ----------------
extern "C" void kernel_launch(void* const* d_in, const int* in_sizes, int n_in,
                              void* d_out, int out_size) {
    const float* ufeat  = (const float*)d_in[0];
    const float* ifeat  = (const float*)d_in[1];
    const float* review = (const float*)d_in[2];
    const float* negs   = (const float*)d_in[3];
    const float* W1     = (const float*)d_in[4];
    const float* W2     = (const float*)d_in[5];
    const int*   src    = (const int*)d_in[6];
    const int*   dst    = (const int*)d_in[7];
    (void)n_in; (void)out_size;

    int E = in_sizes[6];
    int nblk = (E + TILE_M - 1) / TILE_M;
    int nU_blk = (NU + PRE_ROWS - 1) / PRE_ROWS;   // 782
    int nI_blk = (NI + PRE_ROWS - 1) / PRE_ROWS;   // 157

    cudaFuncSetAttribute(precompute_kernel,
                         cudaFuncAttributeMaxDynamicSharedMemorySize, SMEM_PRE);
    precompute_kernel<<<nU_blk + nI_blk, 256, SMEM_PRE>>>(ufeat, ifeat, W1, W2, nU_blk);

    cudaFuncSetAttribute(fused_kernel,
                         cudaFuncAttributeMaxDynamicSharedMemorySize, SMEM_MAIN);
    fused_kernel<<<nblk, 256, SMEM_MAIN>>>(review, negs, src, dst, E, nblk);

    finalize_kernel<<<1, 256>>>((float*)d_out, nblk, E);
}

// round 17
// speedup vs baseline: 1.1771x; 1.0509x over previous
#include <cuda_runtime.h>
#include <cuda_bf16.h>
#include <cstdint>

// ---------------- constants ----------------
#define TEMP_INV 10.0f
#define TILE_M   128

// main-kernel smem layout (bytes)
#define PH   136                  // H tile pitch (bf16)
#define PO   68                   // OUT tile pitch (fp32)
#define OFF_W2   34816            // after sH (128*136*2)
#define OFF_WSUM 51200            // after W2 (16384)
#define SMEM_MAIN 51264           // + 64 wsum

#define NU 50000
#define NI 10000

__device__ float g_partials[8192];
__device__ __align__(16) __nv_bfloat16 g_w2[128 * 64];
__device__ __align__(16) __nv_bfloat16 g_up[NU * 128];
__device__ __align__(16) __nv_bfloat16 g_ip[NI * 128];

// ---------------- PTX helpers ----------------
__device__ __forceinline__ uint32_t sptr(const void* p) {
    return (uint32_t)__cvta_generic_to_shared(p);
}
__device__ __forceinline__ void ldm_x4(uint32_t a, uint32_t& r0, uint32_t& r1,
                                       uint32_t& r2, uint32_t& r3) {
    asm volatile("ldmatrix.sync.aligned.m8n8.x4.shared.b16 {%0,%1,%2,%3}, [%4];"
                 : "=r"(r0), "=r"(r1), "=r"(r2), "=r"(r3) : "r"(a));
}
__device__ __forceinline__ void ldm_x4_t(uint32_t a, uint32_t& r0, uint32_t& r1,
                                         uint32_t& r2, uint32_t& r3) {
    asm volatile("ldmatrix.sync.aligned.m8n8.x4.trans.shared.b16 {%0,%1,%2,%3}, [%4];"
                 : "=r"(r0), "=r"(r1), "=r"(r2), "=r"(r3) : "r"(a));
}
__device__ __forceinline__ void mma16816(float* d, const uint32_t* a,
                                         uint32_t b0, uint32_t b1) {
    asm volatile(
        "mma.sync.aligned.m16n8k16.row.col.f32.bf16.bf16.f32 "
        "{%0,%1,%2,%3}, {%4,%5,%6,%7}, {%8,%9}, {%0,%1,%2,%3};"
        : "+f"(d[0]), "+f"(d[1]), "+f"(d[2]), "+f"(d[3])
        : "r"(a[0]), "r"(a[1]), "r"(a[2]), "r"(a[3]), "r"(b0), "r"(b1));
}
__device__ __forceinline__ void cpa16(uint32_t dst, const void* src) {
    asm volatile("cp.async.ca.shared.global [%0], [%1], 16;"
                 :: "r"(dst), "l"(src) : "memory");
}
__device__ __forceinline__ void cp_commit() {
    asm volatile("cp.async.commit_group;" ::: "memory");
}
template <int N> __device__ __forceinline__ void cp_wait() {
    asm volatile("cp.async.wait_group %0;" :: "n"(N) : "memory");
}
// streaming (evict-first) float4 load — once-read stream stays out of L2 set
__device__ __forceinline__ float4 ldcs4(const float* p) {
    float4 v;
    asm volatile("ld.global.cs.v4.f32 {%0,%1,%2,%3}, [%4];"
                 : "=f"(v.x), "=f"(v.y), "=f"(v.z), "=f"(v.w) : "l"(p));
    return v;
}

// ================= precompute: U' = ufeat@W1u, I' = ifeat@W1i (bf16 out) ====
// (R14 version verbatim: 128-row tiles, occ-2, W1 convert-on-stage, W2 in blk0)
__global__ void __launch_bounds__(256, 2) precompute_kernel(
    const float* __restrict__ ufeat, const float* __restrict__ ifeat,
    const float* __restrict__ W1, const float* __restrict__ W2, int nU_blk)
{
    extern __shared__ char smem[];
    const uint32_t sA_su = sptr(smem);
    const uint32_t sW_su = sA_su + 32768;

    const int tid = threadIdx.x;
    const int lane = tid & 31;
    const int wid = tid >> 5;

    const bool bu = (int)blockIdx.x < nU_blk;
    const int rowbase = (bu ? blockIdx.x : blockIdx.x - nU_blk) * 128;
    const int nrows = bu ? NU : NI;
    const float* __restrict__ srcf = bu ? ufeat : ifeat;
    const float* __restrict__ wsrc = W1 + (bu ? 0 : 128 * 128);
    __nv_bfloat16* __restrict__ outp = bu ? g_up : g_ip;

    if (blockIdx.x == 0) {
        #pragma unroll
        for (int i = tid; i < 128 * 64; i += 256)
            g_w2[i] = __float2bfloat16(W2[i]);
    }

    #pragma unroll
    for (int i = tid; i < 2048; i += 256) {
        int r = i >> 4, u = i & 15;
        const float* p = wsrc + (size_t)r * 128 + u * 8;
        float4 v0 = *(const float4*)p;
        float4 v1 = *(const float4*)(p + 4);
        uint32_t w[4];
        *(__nv_bfloat162*)&w[0] = __floats2bfloat162_rn(v0.x, v0.y);
        *(__nv_bfloat162*)&w[1] = __floats2bfloat162_rn(v0.z, v0.w);
        *(__nv_bfloat162*)&w[2] = __floats2bfloat162_rn(v1.x, v1.y);
        *(__nv_bfloat162*)&w[3] = __floats2bfloat162_rn(v1.z, v1.w);
        uint32_t dsu = sW_su + r * 256 + ((u ^ (r & 7)) << 4);
        asm volatile("st.shared.v4.b32 [%0], {%1,%2,%3,%4};"
                     :: "r"(dsu), "r"(w[0]), "r"(w[1]), "r"(w[2]), "r"(w[3]));
    }

    #pragma unroll
    for (int i = tid; i < 2048; i += 256) {
        int r = i >> 4, u = i & 15;
        int rc = rowbase + r; if (rc >= nrows) rc = nrows - 1;
        const float* p = srcf + (size_t)rc * 128 + u * 8;
        float4 v0 = *(const float4*)p;
        float4 v1 = *(const float4*)(p + 4);
        uint32_t w[4];
        *(__nv_bfloat162*)&w[0] = __floats2bfloat162_rn(v0.x, v0.y);
        *(__nv_bfloat162*)&w[1] = __floats2bfloat162_rn(v0.z, v0.w);
        *(__nv_bfloat162*)&w[2] = __floats2bfloat162_rn(v1.x, v1.y);
        *(__nv_bfloat162*)&w[3] = __floats2bfloat162_rn(v1.z, v1.w);
        uint32_t dsu = sA_su + r * 256 + ((u ^ (r & 7)) << 4);
        asm volatile("st.shared.v4.b32 [%0], {%1,%2,%3,%4};"
                     :: "r"(dsu), "r"(w[0]), "r"(w[1]), "r"(w[2]), "r"(w[3]));
    }
    __syncthreads();

    float acc[2][8][4];
    #pragma unroll
    for (int a = 0; a < 2; ++a)
        #pragma unroll
        for (int b = 0; b < 8; ++b)
            #pragma unroll
            for (int c = 0; c < 4; ++c) acc[a][b][c] = 0.f;

    const int wm = (wid & 3) * 32;
    const int wn = (wid >> 2) * 64;

    #pragma unroll
    for (int ks = 0; ks < 8; ++ks) {
        const int u = ks * 2 + (lane >> 4);
        uint32_t a0[4], a1[4];
        {
            int r = wm + (lane & 15);
            ldm_x4(sA_su + r * 256 + ((u ^ (r & 7)) << 4), a0[0], a0[1], a0[2], a0[3]);
            r += 16;
            ldm_x4(sA_su + r * 256 + ((u ^ (r & 7)) << 4), a1[0], a1[1], a1[2], a1[3]);
        }
        const int lr = ks * 16 + (lane & 15);
        #pragma unroll
        for (int nb = 0; nb < 4; ++nb) {
            int cu = (wn >> 3) + nb * 2 + (lane >> 4);
            uint32_t b0, b1, b2, b3;
            ldm_x4_t(sW_su + lr * 256 + ((cu ^ (lr & 7)) << 4), b0, b1, b2, b3);
            mma16816(acc[0][2 * nb],     a0, b0, b1);
            mma16816(acc[0][2 * nb + 1], a0, b2, b3);
            mma16816(acc[1][2 * nb],     a1, b0, b1);
            mma16816(acc[1][2 * nb + 1], a1, b2, b3);
        }
    }

    #pragma unroll
    for (int mi = 0; mi < 2; ++mi)
        #pragma unroll
        for (int nj = 0; nj < 8; ++nj) {
            int row = wm + mi * 16 + (lane >> 2);
            int col = wn + nj * 8 + (lane & 3) * 2;
            float* c = acc[mi][nj];
            int gr0 = rowbase + row, gr1 = gr0 + 8;
            if (gr0 < nrows)
                *(__nv_bfloat162*)&outp[(size_t)gr0 * 128 + col] =
                    __floats2bfloat162_rn(c[0], c[1]);
            if (gr1 < nrows)
                *(__nv_bfloat162*)&outp[(size_t)gr1 * 128 + col] =
                    __floats2bfloat162_rn(c[2], c[3]);
        }
}

// ================= fused per-edge kernel: per-warp pipeline, 1 barrier ======
// (R14 hot path; gather widened to LDG.128, 2 rows per warp-instruction)
__global__ void __launch_bounds__(256, 3) fused_kernel(
    const float* __restrict__ review, const float* __restrict__ negs,
    const int* __restrict__ src, const int* __restrict__ dst, int E,
    int nblk_unused)
{
    extern __shared__ char smem[];
    __nv_bfloat16* sH = (__nv_bfloat16*)smem;
    const uint32_t w2_su = sptr(smem) + OFF_W2;
    float* wSums = (float*)(smem + OFF_WSUM);

    const int tid = threadIdx.x;
    const int lane = tid & 31;
    const int wid = tid >> 5;
    const int base = blockIdx.x * TILE_M;
    const int m0 = wid * 16;

    // stage W2 (swizzled) via cp.async — fetch overlaps the gather below
    #pragma unroll
    for (int i = tid; i < 1024; i += 256) {
        int r = i >> 3, u = i & 7;
        cpa16(w2_su + r * 128 + ((u ^ (r & 7)) << 4), g_w2 + (size_t)r * 64 + u * 8);
    }
    cp_commit();

    // per-warp indices: lanes 0-15 carry src, lanes 16-31 carry dst
    int idxv;
    {
        int e0 = base + m0 + (lane & 15);
        bool ok = (e0 < E);
        idxv = (lane < 16) ? (ok ? src[e0] : src[0])
                           : (ok ? dst[e0] : dst[0]);
    }

    // per-warp gather, TWO rows per iteration: 16 lanes cover one 256B row
    // (uint4 each). Half the load instructions of the row-at-a-time form,
    // 4 lines per warp-instruction (still gentle on the L1tex queue).
    #pragma unroll 4
    for (int it = 0; it < 8; ++it) {
        const int rsel = it * 2 + (lane >> 4);            // row within warp tile
        const int si = __shfl_sync(0xffffffffu, idxv, rsel);
        const int di = __shfl_sync(0xffffffffu, idxv, 16 + rsel);
        const int part = lane & 15;                       // 16B chunk in row
        uint4 uu = *((const uint4*)(g_up + (size_t)si * 128) + part);
        uint4 ii = *((const uint4*)(g_ip + (size_t)di * 128) + part);
        uint32_t* uw = (uint32_t*)&uu;
        uint32_t* iw = (uint32_t*)&ii;
        uint4 hh;
        uint32_t* hw = (uint32_t*)&hh;
        #pragma unroll
        for (int j = 0; j < 4; ++j) {
            float2 fu = __bfloat1622float2(*(__nv_bfloat162*)&uw[j]);
            float2 fi = __bfloat1622float2(*(__nv_bfloat162*)&iw[j]);
            *(__nv_bfloat162*)&hw[j] = __floats2bfloat162_rn(
                fmaxf(fu.x + fi.x, 0.f), fmaxf(fu.y + fi.y, 0.f));
        }
        *(uint4*)&sH[(m0 + rsel) * PH + part * 8] = hh;
    }

    cp_wait<0>();
    __syncthreads();   // W2 ready; also makes warp's own gather cross-lane visible

    // GEMM2 (per-warp): OUT[m0:m0+16, 0:64] = H[m0:m0+16, :] @ W2
    float acc2[8][4];
    #pragma unroll
    for (int b = 0; b < 8; ++b)
        #pragma unroll
        for (int c = 0; c < 4; ++c) acc2[b][c] = 0.f;

    #pragma unroll
    for (int k = 0; k < 8; ++k) {
        int kg = k * 16;
        uint32_t a[4];
        ldm_x4(sptr(&sH[(m0 + (lane & 15)) * PH + kg + ((lane >> 4) << 3)]),
               a[0], a[1], a[2], a[3]);
        const int lr = kg + (lane & 15);
        #pragma unroll
        for (int nb = 0; nb < 4; ++nb) {
            int cu = nb * 2 + (lane >> 4);
            uint32_t b0, b1, b2, b3;
            ldm_x4_t(w2_su + lr * 128 + ((cu ^ (lr & 7)) << 4), b0, b1, b2, b3);
            mma16816(acc2[2 * nb],     a, b0, b1);
            mma16816(acc2[2 * nb + 1], a, b2, b3);
        }
    }

    // warp's ldmatrix reads of its own rows are complete (warp-synchronous);
    // overwrite the SAME byte range with fp32 OUT.
    float* sOUT = (float*)smem;
    #pragma unroll
    for (int nj = 0; nj < 8; ++nj) {
        int row = m0 + (lane >> 2);
        int col = nj * 8 + (lane & 3) * 2;
        *(float2*)&sOUT[row * PO + col]       = make_float2(acc2[nj][0], acc2[nj][1]);
        *(float2*)&sOUT[(row + 8) * PO + col] = make_float2(acc2[nj][2], acc2[nj][3]);
    }
    __syncwarp();   // cross-lane visibility of OUT within the warp

    // ---- epilogue v4: 4 lanes per edge, 8 edges/pass, 2 shuffle rounds ----
    float lsum = 0.f;
    {
        const int eg = lane >> 2;           // edge within pass group (0..7)
        const int qb = (lane & 3) << 4;     // dim base (0,16,32,48)

        #pragma unroll
        for (int pass = 0; pass < 2; ++pass) {
            const int r = m0 + pass * 8 + eg;
            const long e = base + r;
            const bool valid = (e < E);
            const long ec = valid ? e : 0;
            const float* __restrict__ pr = review + ec * 64 + qb;
            const float* __restrict__ ng = negs + ec * 320 + qb;

            float q[16];
            #pragma unroll
            for (int i = 0; i < 4; ++i) {
                float4 t = *(const float4*)&sOUT[r * PO + qb + 4 * i];
                q[4*i] = t.x; q[4*i+1] = t.y; q[4*i+2] = t.z; q[4*i+3] = t.w;
            }

            float v[13];
            float qq = 0.f;
            #pragma unroll
            for (int i = 0; i < 16; ++i) qq += q[i] * q[i];
            v[0] = qq;
            float qp = 0.f, pp = 0.f;
            #pragma unroll
            for (int i = 0; i < 4; ++i) {
                float4 p4 = ldcs4(pr + 4 * i);
                qp += q[4*i]*p4.x + q[4*i+1]*p4.y + q[4*i+2]*p4.z + q[4*i+3]*p4.w;
                pp += p4.x*p4.x + p4.y*p4.y + p4.z*p4.z + p4.w*p4.w;
            }
            v[1] = qp; v[2] = pp;
            #pragma unroll
            for (int m = 0; m < 5; ++m) {
                const float* nm = ng + m * 64;
                float dq = 0.f, dn = 0.f;
                #pragma unroll
                for (int i = 0; i < 4; ++i) {
                    float4 n4 = ldcs4(nm + 4 * i);
                    dq += q[4*i]*n4.x + q[4*i+1]*n4.y + q[4*i+2]*n4.z + q[4*i+3]*n4.w;
                    dn += n4.x*n4.x + n4.y*n4.y + n4.z*n4.z + n4.w*n4.w;
                }
                v[3 + 2 * m] = dq;
                v[4 + 2 * m] = dn;
            }

            #pragma unroll
            for (int j = 0; j < 13; ++j)
                v[j] += __shfl_xor_sync(0xffffffffu, v[j], 1);
            #pragma unroll
            for (int j = 0; j < 13; ++j)
                v[j] += __shfl_xor_sync(0xffffffffu, v[j], 2);

            float rq = rsqrtf(v[0]);
            float pos = v[1] * rq * rsqrtf(v[2]) * TEMP_INV;
            float mx = pos;
            float lg[5];
            #pragma unroll
            for (int m = 0; m < 5; ++m) {
                lg[m] = v[3 + 2 * m] * rq * rsqrtf(v[4 + 2 * m]) * TEMP_INV;
                mx = fmaxf(mx, lg[m]);
            }
            float s = __expf(pos - mx);
            #pragma unroll
            for (int m = 0; m < 5; ++m) s += __expf(lg[m] - mx);
            float loss = mx + __logf(s) - pos;
            if (valid && (lane & 3) == 0) lsum += loss;
        }
    }

    #pragma unroll
    for (int off = 16; off > 0; off >>= 1)
        lsum += __shfl_xor_sync(0xffffffffu, lsum, off);

    if (lane == 0) wSums[wid] = lsum;
    __syncthreads();
    if (tid == 0) {
        float bs = 0.f;
        #pragma unroll
        for (int w = 0; w < 8; ++w) bs += wSums[w];
        g_partials[blockIdx.x] = bs;
    }
}

// ---------------- finalize ----------------
__global__ void finalize_kernel(float* out, int nblk, int E) {
    __shared__ float sh[256];
    float s = 0.f;
    for (int i = threadIdx.x; i < nblk; i += 256) s += g_partials[i];
    sh[threadIdx.x] = s;
    __syncthreads();
    for (int st = 128; st > 0; st >>= 1) {
        if (threadIdx.x < st) sh[threadIdx.x] += sh[threadIdx.x + st];
        __syncthreads();
    }
    if (threadIdx.x == 0) out[0] = sh[0] / (float)E;
}

// ---------------- launch ----------------
extern "C" void kernel_launch(void* const* d_in, const int* in_sizes, int n_in,
                              void* d_out, int out_size) {
    const float* ufeat  = (const float*)d_in[0];
    const float* ifeat  = (const float*)d_in[1];
    const float* review = (const float*)d_in[2];
    const float* negs   = (const float*)d_in[3];
    const float* W1     = (const float*)d_in[4];
    const float* W2     = (const float*)d_in[5];
    const int*   src    = (const int*)d_in[6];
    const int*   dst    = (const int*)d_in[7];
    (void)n_in; (void)out_size;

    int E = in_sizes[6];
    int nblk = (E + TILE_M - 1) / TILE_M;
    int nU_blk = (NU + 127) / 128;
    int nI_blk = (NI + 127) / 128;

    cudaFuncSetAttribute(precompute_kernel,
                         cudaFuncAttributeMaxDynamicSharedMemorySize, 65536);
    precompute_kernel<<<nU_blk + nI_blk, 256, 65536>>>(ufeat, ifeat, W1, W2, nU_blk);

    cudaFuncSetAttribute(fused_kernel,
                         cudaFuncAttributeMaxDynamicSharedMemorySize, SMEM_MAIN);
    fused_kernel<<<nblk, 256, SMEM_MAIN>>>(review, negs, src, dst, E, nblk);

    finalize_kernel<<<1, 256>>>((float*)d_out, nblk, E);
}